// round 3
// baseline (speedup 1.0000x reference)
#include <cuda_runtime.h>
#include <math.h>

// Problem constants (fixed by the dataset)
#define VOCAB   32000
#define NBL     128        // B*L
#define NK      64         // H = 8 heads x 8

// Main-kernel tiling
#define BM      64         // bl tile (grid.y = 2)
#define BN      64         // vocab tile (grid.x = 500)
#define KC      16         // k chunk (4 chunks)
#define TM      8          // bl rows per thread (4 pairs)
#define TN      8          // vocab cols per thread
#define NTHR    64         // (BM/TM)*(BN/TN)

typedef unsigned long long u64;

// ---------------------------------------------------------------------------
// Packed f32x2 helpers
// ---------------------------------------------------------------------------
__device__ __forceinline__ u64 pk(float x, float y) {
    u64 r; asm("mov.b64 %0, {%1, %2};" : "=l"(r) : "f"(x), "f"(y)); return r;
}
__device__ __forceinline__ void upk(u64 a, float& x, float& y) {
    asm("mov.b64 {%0, %1}, %2;" : "=f"(x), "=f"(y) : "l"(a));
}
__device__ __forceinline__ u64 mul2(u64 a, u64 b) {
    u64 r; asm("mul.rn.f32x2 %0, %1, %2;" : "=l"(r) : "l"(a), "l"(b)); return r;
}
__device__ __forceinline__ u64 fma2(u64 a, u64 b, u64 c) {
    u64 r; asm("fma.rn.f32x2 %0, %1, %2, %3;" : "=l"(r) : "l"(a), "l"(b), "l"(c)); return r;
}

// ---------------------------------------------------------------------------
// Device scratch (static — no allocation)
// ---------------------------------------------------------------------------
__device__ float2 g_v[NK * VOCAB];     // [k][v] = (e^-vp, e^+vp)
__device__ float  g_cp[NK * NBL];      // [k][bl] = W[h]*a*cos(p - iph)   (adjacent bl = u64 pair)
__device__ float  g_ep[NK * NBL];      // [k][bl] = e^freq
__device__ float  g_em[NK * NBL];      // [k][bl] = e^-freq

// ---------------------------------------------------------------------------
// Prep: blocks 0..999 transpose+exp vocab patterns; block 1000 does bl coeffs
// ---------------------------------------------------------------------------
__global__ void __launch_bounds__(256)
prep_kernel(const float* __restrict__ freqs,
            const float* __restrict__ amps,
            const float* __restrict__ phases,
            const float* __restrict__ vp,
            const float* __restrict__ iph,
            const float* __restrict__ W) {
    if (blockIdx.x < 1000) {
        __shared__ float s[NK * 33];            // padded 32v x 64k transpose tile
        const int vbase = blockIdx.x * 32;
        #pragma unroll
        for (int it = 0; it < 8; ++it) {        // coalesced read vp[v][k]
            int j = threadIdx.x + it * 256;
            int v = j >> 6, k = j & 63;
            s[k * 33 + v] = vp[(long)(vbase + v) * NK + k];
        }
        __syncthreads();
        #pragma unroll
        for (int it = 0; it < 8; ++it) {        // coalesced write [k][v] float2
            int j = threadIdx.x + it * 256;
            int k = j >> 5, v = j & 31;
            float x = s[k * 33 + v];
            g_v[(long)k * VOCAB + vbase + v] = make_float2(expf(-x), expf(x));
        }
    } else {
        #pragma unroll 4
        for (int it = 0; it < (NBL * NK) / 256; ++it) {
            int idx = threadIdx.x + it * 256;   // idx = bl*NK + k
            int bl = idx >> 6, k = idx & 63;
            float cp = amps[idx] * cosf(phases[idx] - iph[k]) * W[k >> 3];
            float f  = freqs[idx];
            int o = k * NBL + bl;
            g_cp[o] = cp;
            g_ep[o] = expf(f);
            g_em[o] = expf(-f);
        }
    }
}

// ---------------------------------------------------------------------------
// Main: out[bl][v] = sum_k cp * min(e^f * e^-vp, e^-f * e^vp) + bias
// bl side as f32x2 pairs; vocab side duplicated (x,x) once per smem tile.
// ---------------------------------------------------------------------------
__global__ void __launch_bounds__(NTHR, 8)
main_kernel(float* __restrict__ out, const float* __restrict__ bptr) {
    __shared__ u64 s_vd[KC * BN * 2];    // [kl][v] -> (em,em),(ep,ep)   16KB
    __shared__ u64 s_cp[KC * (BM / 2)];  // [kl][pair]                    4KB
    __shared__ u64 s_ep[KC * (BM / 2)];
    __shared__ u64 s_em[KC * (BM / 2)];

    const int tid    = threadIdx.x;
    const int vbase  = blockIdx.x * BN;
    const int blbase = blockIdx.y * BM;
    const int pbase  = blbase >> 1;           // global bl-pair base

    const int vcol  = tid & 7;                // 8 vocab groups
    const int blrow = tid >> 3;               // 8 bl groups (x8 rows)
    const int p0    = blrow * (TM / 2);       // 4 local pairs

    u64 acc[4][TN];
    #pragma unroll
    for (int i = 0; i < 4; ++i)
        #pragma unroll
        for (int j = 0; j < TN; ++j) acc[i][j] = 0ull;

    for (int kc = 0; kc < NK; kc += KC) {
        // --- fill vocab dup tile: global float2 -> smem float4 (em,em,ep,ep)
        #pragma unroll
        for (int it = 0; it < KC; ++it) {
            float2 q = g_v[(long)(kc + it) * VOCAB + vbase + tid];
            ((float4*)s_vd)[it * BN + tid] = make_float4(q.x, q.x, q.y, q.y);
        }
        // --- fill bl pair tiles: 16k x 32 pairs per plane, 8 u64/thread
        #pragma unroll
        for (int it = 0; it < (KC * (BM / 2)) / NTHR; ++it) {
            int idx = it * NTHR + tid;
            int kl = idx >> 5, p = idx & 31;
            int src = ((kc + kl) * NBL >> 1) + pbase + p;
            s_cp[idx] = ((const u64*)g_cp)[src];
            s_ep[idx] = ((const u64*)g_ep)[src];
            s_em[idx] = ((const u64*)g_em)[src];
        }
        __syncthreads();

        #pragma unroll 4
        for (int kl = 0; kl < KC; ++kl) {
            const int bb = kl * (BM / 2) + p0;
            ulonglong2 c01 = *(const ulonglong2*)&s_cp[bb];
            ulonglong2 c23 = *(const ulonglong2*)&s_cp[bb + 2];
            ulonglong2 e01 = *(const ulonglong2*)&s_ep[bb];
            ulonglong2 e23 = *(const ulonglong2*)&s_ep[bb + 2];
            ulonglong2 m01 = *(const ulonglong2*)&s_em[bb];
            ulonglong2 m23 = *(const ulonglong2*)&s_em[bb + 2];
            const ulonglong2* vv = (const ulonglong2*)&s_vd[(kl * BN + vcol * TN) * 2];

            #pragma unroll
            for (int j = 0; j < TN; ++j) {
                ulonglong2 d = vv[j];           // d.x=(em,em)  d.y=(ep,ep)
                {
                    u64 t1 = mul2(e01.x, d.x), t2 = mul2(m01.x, d.y);
                    float a0,a1,b0,b1; upk(t1,a0,a1); upk(t2,b0,b1);
                    acc[0][j] = fma2(c01.x, pk(fminf(a0,b0), fminf(a1,b1)), acc[0][j]);
                }
                {
                    u64 t1 = mul2(e01.y, d.x), t2 = mul2(m01.y, d.y);
                    float a0,a1,b0,b1; upk(t1,a0,a1); upk(t2,b0,b1);
                    acc[1][j] = fma2(c01.y, pk(fminf(a0,b0), fminf(a1,b1)), acc[1][j]);
                }
                {
                    u64 t1 = mul2(e23.x, d.x), t2 = mul2(m23.x, d.y);
                    float a0,a1,b0,b1; upk(t1,a0,a1); upk(t2,b0,b1);
                    acc[2][j] = fma2(c23.x, pk(fminf(a0,b0), fminf(a1,b1)), acc[2][j]);
                }
                {
                    u64 t1 = mul2(e23.y, d.x), t2 = mul2(m23.y, d.y);
                    float a0,a1,b0,b1; upk(t1,a0,a1); upk(t2,b0,b1);
                    acc[3][j] = fma2(c23.y, pk(fminf(a0,b0), fminf(a1,b1)), acc[3][j]);
                }
            }
        }
        __syncthreads();
    }

    // Epilogue: accs are pairs over bl (rows 2p, 2p+1) for each v column
    const float bias = bptr[0];
    const long colbase = vbase + vcol * TN;
    #pragma unroll
    for (int p = 0; p < 4; ++p) {
        float lo[TN], hi[TN];
        #pragma unroll
        for (int j = 0; j < TN; ++j) { upk(acc[p][j], lo[j], hi[j]); }
        long r0 = (long)(blbase + blrow * TM + 2 * p) * VOCAB + colbase;
        long r1 = r0 + VOCAB;
        *(float4*)&out[r0]     = make_float4(lo[0]+bias, lo[1]+bias, lo[2]+bias, lo[3]+bias);
        *(float4*)&out[r0 + 4] = make_float4(lo[4]+bias, lo[5]+bias, lo[6]+bias, lo[7]+bias);
        *(float4*)&out[r1]     = make_float4(hi[0]+bias, hi[1]+bias, hi[2]+bias, hi[3]+bias);
        *(float4*)&out[r1 + 4] = make_float4(hi[4]+bias, hi[5]+bias, hi[6]+bias, hi[7]+bias);
    }
}

// ---------------------------------------------------------------------------
extern "C" void kernel_launch(void* const* d_in, const int* in_sizes, int n_in,
                              void* d_out, int out_size) {
    const float* freqs  = (const float*)d_in[0];
    const float* amps   = (const float*)d_in[1];
    const float* phases = (const float*)d_in[2];
    const float* vp     = (const float*)d_in[3];
    const float* iph    = (const float*)d_in[4];
    const float* W      = (const float*)d_in[5];
    const float* b      = (const float*)d_in[6];
    float* out = (float*)d_out;

    prep_kernel<<<1001, 256>>>(freqs, amps, phases, vp, iph, W);

    // Allow maximum smem carveout so 7-8 CTAs (28KB each) fit per SM
    cudaFuncSetAttribute(main_kernel, cudaFuncAttributePreferredSharedMemoryCarveout, 100);

    dim3 grid(VOCAB / BN, NBL / BM);   // (500, 2)
    main_kernel<<<grid, NTHR>>>(out, b);
    (void)in_sizes; (void)n_in; (void)out_size;
}

// round 4
// speedup vs baseline: 2.4507x; 2.4507x over previous
#include <cuda_runtime.h>
#include <math.h>

// Problem constants (fixed by the dataset)
#define VOCAB   32000
#define NBL     128        // B*L
#define NK      64         // 8 heads x 8

// Main-kernel tiling
#define BN      32         // vocab tile -> grid.x = 1000
#define BM      128        // full bl dimension per CTA
#define KC      16         // k chunk for the bl-coefficient smem tiles
#define NTHR    256        // 8 vcol groups x 32 blrow groups

typedef unsigned long long u64;

// ---------------------------------------------------------------------------
// Packed f32x2 helpers
// ---------------------------------------------------------------------------
__device__ __forceinline__ u64 pk(float x, float y) {
    u64 r; asm("mov.b64 %0, {%1, %2};" : "=l"(r) : "f"(x), "f"(y)); return r;
}
__device__ __forceinline__ void upk(u64 a, float& x, float& y) {
    asm("mov.b64 {%0, %1}, %2;" : "=f"(x), "=f"(y) : "l"(a));
}
__device__ __forceinline__ u64 mul2(u64 a, u64 b) {
    u64 r; asm("mul.rn.f32x2 %0, %1, %2;" : "=l"(r) : "l"(a), "l"(b)); return r;
}
__device__ __forceinline__ u64 fma2(u64 a, u64 b, u64 c) {
    u64 r; asm("fma.rn.f32x2 %0, %1, %2, %3;" : "=l"(r) : "l"(a), "l"(b), "l"(c)); return r;
}

// ---------------------------------------------------------------------------
// Device scratch: per-(k,bl) coefficients (adjacent bl form u64 pairs)
// ---------------------------------------------------------------------------
__device__ __align__(16) float g_cp[NK * NBL];   // [k][bl] = W[h]*a*cos(p - iph)
__device__ __align__(16) float g_ep[NK * NBL];   // [k][bl] = e^freq
__device__ __align__(16) float g_em[NK * NBL];   // [k][bl] = e^-freq

// ---------------------------------------------------------------------------
// Tiny prep: 8192 bl coefficients
// ---------------------------------------------------------------------------
__global__ void prep_bl(const float* __restrict__ freqs,
                        const float* __restrict__ amps,
                        const float* __restrict__ phases,
                        const float* __restrict__ iph,
                        const float* __restrict__ W) {
    int idx = blockIdx.x * 256 + threadIdx.x;   // idx = bl*NK + k
    int bl = idx >> 6, k = idx & 63;
    float cp = amps[idx] * cosf(phases[idx] - iph[k]) * W[k >> 3];
    float f  = freqs[idx];
    int o = k * NBL + bl;
    g_cp[o] = cp;
    g_ep[o] = expf(f);
    g_em[o] = expf(-f);
}

// ---------------------------------------------------------------------------
// Main: out[bl][v] = sum_k cp * min(e^f * e^-vp, e^-f * e^vp) + bias
//  - vocab exp computed in-kernel (no global table), duplicated (em,em,ep,ep)
//    and stored interleaved [k][j][vcol] so every inner LDS.128 is 1 wavefront
//  - bl side: full 128 rows as u64 pairs, k-chunked smem, warp-broadcast loads
// ---------------------------------------------------------------------------
__global__ void __launch_bounds__(NTHR, 3)
main_kernel(float* __restrict__ out,
            const float* __restrict__ vp,
            const float* __restrict__ bptr) {
    extern __shared__ char sm[];
    ulonglong2* s_v  = (ulonglong2*)sm;                 // [NK][32] (em,em,ep,ep) 32KB
    u64*        s_cp = (u64*)(sm + 32768);              // [KC][BM/2]  8KB
    u64*        s_ep = s_cp + KC * (BM / 2);            //             8KB
    u64*        s_em = s_ep + KC * (BM / 2);            //             8KB

    const int tid   = threadIdx.x;
    const int vbase = blockIdx.x * BN;

    // --- In-kernel vocab exp fill: 32 v-columns x 64 k, duplicated pairs ---
    #pragma unroll
    for (int it = 0; it < (BN * NK) / NTHR; ++it) {     // 8 iters
        int idx = tid + it * NTHR;                      // 0..2047
        int v = idx >> 6, k = idx & 63;                 // coalesced LDG over k
        float x   = vp[(long)(vbase + v) * NK + k];
        float epv = __expf(x);
        float emv = __expf(-x);
        // layout: element (k*32 + j*8 + vcol) with v = vcol*4 + j
        ((float4*)s_v)[k * 32 + (v & 3) * 8 + (v >> 2)] =
            make_float4(emv, emv, epv, epv);
    }

    const int vcol  = tid & 7;          // 8 vocab groups x TN=4
    const int blrow = tid >> 3;         // 32 bl groups x TM=4 rows
    const int p0    = blrow * 2;        // first bl-pair of this thread

    u64 acc0[4], acc1[4];
    #pragma unroll
    for (int j = 0; j < 4; ++j) { acc0[j] = 0ull; acc1[j] = 0ull; }

    const float bias = bptr[0];

    for (int kc = 0; kc < NK; kc += KC) {
        // --- fill bl chunk: 3 planes x 512 ulonglong2, fully coalesced ---
        const ulonglong2* gcp = (const ulonglong2*)g_cp + kc * (NBL / 4);
        const ulonglong2* gep = (const ulonglong2*)g_ep + kc * (NBL / 4);
        const ulonglong2* gem = (const ulonglong2*)g_em + kc * (NBL / 4);
        #pragma unroll
        for (int it = 0; it < (KC * (BM / 2) / 2) / NTHR; ++it) {   // 2 iters
            int idx = tid + it * NTHR;
            ((ulonglong2*)s_cp)[idx] = gcp[idx];
            ((ulonglong2*)s_ep)[idx] = gep[idx];
            ((ulonglong2*)s_em)[idx] = gem[idx];
        }
        __syncthreads();   // fill visible (covers vocab fill on first iter)

        #pragma unroll
        for (int kl = 0; kl < KC; ++kl) {
            const int bb = kl * (BM / 2) + p0;
            ulonglong2 cp = *(const ulonglong2*)(s_cp + bb);   // broadcast, 1 WF
            ulonglong2 ep = *(const ulonglong2*)(s_ep + bb);
            ulonglong2 em = *(const ulonglong2*)(s_em + bb);
            const ulonglong2* vv = s_v + (kc + kl) * 32 + vcol;

            #pragma unroll
            for (int j = 0; j < 4; ++j) {
                ulonglong2 d = vv[j * 8];          // d.x=(em,em)  d.y=(ep,ep)
                {
                    u64 t1 = mul2(ep.x, d.x), t2 = mul2(em.x, d.y);
                    float a0, a1, b0, b1; upk(t1, a0, a1); upk(t2, b0, b1);
                    acc0[j] = fma2(cp.x, pk(fminf(a0, b0), fminf(a1, b1)), acc0[j]);
                }
                {
                    u64 t1 = mul2(ep.y, d.x), t2 = mul2(em.y, d.y);
                    float a0, a1, b0, b1; upk(t1, a0, a1); upk(t2, b0, b1);
                    acc1[j] = fma2(cp.y, pk(fminf(a0, b0), fminf(a1, b1)), acc1[j]);
                }
            }
        }
        __syncthreads();   // all reads done before next chunk overwrite
    }

    // --- Epilogue: 4 rows x 4 cols per thread, coalesced STG.128 ---
    {
        long base = (long)(4 * blrow) * VOCAB + vbase + vcol * 4;
        float l0, h0, l1, h1, l2, h2, l3, h3;

        upk(acc0[0], l0, h0); upk(acc0[1], l1, h1);
        upk(acc0[2], l2, h2); upk(acc0[3], l3, h3);
        *(float4*)&out[base]         = make_float4(l0 + bias, l1 + bias, l2 + bias, l3 + bias);
        *(float4*)&out[base + VOCAB] = make_float4(h0 + bias, h1 + bias, h2 + bias, h3 + bias);

        upk(acc1[0], l0, h0); upk(acc1[1], l1, h1);
        upk(acc1[2], l2, h2); upk(acc1[3], l3, h3);
        *(float4*)&out[base + 2L * VOCAB] = make_float4(l0 + bias, l1 + bias, l2 + bias, l3 + bias);
        *(float4*)&out[base + 3L * VOCAB] = make_float4(h0 + bias, h1 + bias, h2 + bias, h3 + bias);
    }
}

// ---------------------------------------------------------------------------
extern "C" void kernel_launch(void* const* d_in, const int* in_sizes, int n_in,
                              void* d_out, int out_size) {
    const float* freqs  = (const float*)d_in[0];
    const float* amps   = (const float*)d_in[1];
    const float* phases = (const float*)d_in[2];
    const float* vp     = (const float*)d_in[3];
    const float* iph    = (const float*)d_in[4];
    const float* W      = (const float*)d_in[5];
    const float* b      = (const float*)d_in[6];
    float* out = (float*)d_out;

    prep_bl<<<(NBL * NK) / 256, 256>>>(freqs, amps, phases, iph, W);

    const int smem_bytes = 32768 + 3 * KC * (BM / 2) * (int)sizeof(u64);  // 57344
    cudaFuncSetAttribute(main_kernel, cudaFuncAttributeMaxDynamicSharedMemorySize, smem_bytes);

    main_kernel<<<VOCAB / BN, NTHR, smem_bytes>>>(out, vp, b);
    (void)in_sizes; (void)n_in; (void)out_size;
}

// round 5
// speedup vs baseline: 2.6170x; 1.0678x over previous
#include <cuda_runtime.h>
#include <math.h>

// Problem constants (fixed by the dataset)
#define VOCAB   32000
#define NBL     128        // B*L
#define NK      64         // 8 heads x 8

// Main-kernel tiling: 128 threads, each owns 8 bl-rows x 8 vocab-cols
#define BM      128        // full bl dimension per CTA
#define BN      64         // vocab tile -> grid.x = 500
#define KC      16         // k chunk for bl-coefficient smem
#define NTHR    128

typedef unsigned long long u64;

// ---------------------------------------------------------------------------
// Packed f32x2 helpers
// ---------------------------------------------------------------------------
__device__ __forceinline__ u64 pk(float x, float y) {
    u64 r; asm("mov.b64 %0, {%1, %2};" : "=l"(r) : "f"(x), "f"(y)); return r;
}
__device__ __forceinline__ void upk(u64 a, float& x, float& y) {
    asm("mov.b64 {%0, %1}, %2;" : "=f"(x), "=f"(y) : "l"(a));
}
__device__ __forceinline__ u64 mul2(u64 a, u64 b) {
    u64 r; asm("mul.rn.f32x2 %0, %1, %2;" : "=l"(r) : "l"(a), "l"(b)); return r;
}
__device__ __forceinline__ u64 fma2(u64 a, u64 b, u64 c) {
    u64 r; asm("fma.rn.f32x2 %0, %1, %2, %3;" : "=l"(r) : "l"(a), "l"(b), "l"(c)); return r;
}
__device__ __forceinline__ u64 add2(u64 a, u64 b) {
    u64 r; asm("add.rn.f32x2 %0, %1, %2;" : "=l"(r) : "l"(a), "l"(b)); return r;
}

// ---------------------------------------------------------------------------
// Device scratch: per-(k,bl) coefficients
// ---------------------------------------------------------------------------
__device__ __align__(16) float g_cp[NK * NBL];   // [k][bl] = W[h]*a*cos(p - iph)
__device__ __align__(16) float g_ep[NK * NBL];   // [k][bl] = e^freq
__device__ __align__(16) float g_em[NK * NBL];   // [k][bl] = e^-freq

__global__ void prep_bl(const float* __restrict__ freqs,
                        const float* __restrict__ amps,
                        const float* __restrict__ phases,
                        const float* __restrict__ iph,
                        const float* __restrict__ W) {
    int idx = blockIdx.x * 256 + threadIdx.x;   // idx = bl*NK + k
    int bl = idx >> 6, k = idx & 63;
    float cp = amps[idx] * cosf(phases[idx] - iph[k]) * W[k >> 3];
    float f  = freqs[idx];
    int o = k * NBL + bl;
    g_cp[o] = cp;
    g_ep[o] = expf(f);
    g_em[o] = expf(-f);
}

// ---------------------------------------------------------------------------
// Main: out[bl][v] = sum_k cp * min(e^f * e^-vp, e^-f * e^vp) + bias
//  - vocab smem: [k][pair] float4 = (em_v0, em_v1, ep_v0, ep_v1), pair index
//    p = j*8 + c with v0 = c*8 + 2j  -> conflict-free LDS.128 in the loop
//  - bl smem: 3 scalar planes, k-chunked; LDS.32 broadcasts + register dups
// ---------------------------------------------------------------------------
__global__ void __launch_bounds__(NTHR, 4)
main_kernel(float* __restrict__ out,
            const float* __restrict__ vp,
            const float* __restrict__ bptr) {
    extern __shared__ char sm[];
    float4* s_v  = (float4*)sm;                 // [NK][32] pairs     32KB
    float*  s_cp = (float*)(sm + 32768);        // [KC][BM]            8KB
    float*  s_ep = s_cp + KC * BM;              //                     8KB
    float*  s_em = s_ep + KC * BM;              //                     8KB

    const int tid   = threadIdx.x;
    const int vbase = blockIdx.x * BN;

    // --- In-kernel vocab exp fill: 2048 (k, v-pair) items, 16 per thread ---
    #pragma unroll
    for (int it = 0; it < 16; ++it) {
        int idx = it * NTHR + tid;          // warp: k fixed, p = lane
        int k = idx >> 5;
        int p = idx & 31;
        int v0 = (p & 7) * 8 + (p >> 3) * 2;
        float x0 = vp[(long)(vbase + v0) * NK + k];
        float x1 = vp[(long)(vbase + v0 + 1) * NK + k];
        s_v[k * 32 + p] = make_float4(__expf(-x0), __expf(-x1),
                                      __expf(x0),  __expf(x1));
    }

    const int c  = tid & 7;                 // vocab group: cols c*8 .. c*8+7
    const int r0 = (tid >> 3) * 8;          // first of 8 bl rows

    u64 acc[8][4];
    #pragma unroll
    for (int i = 0; i < 8; ++i)
        #pragma unroll
        for (int j = 0; j < 4; ++j) acc[i][j] = 0ull;

    for (int kc = 0; kc < NK; kc += KC) {
        // --- bl chunk fill: 3 planes x 512 float4, coalesced ---
        const float4* gc = (const float4*)(g_cp + kc * NBL);
        const float4* ge = (const float4*)(g_ep + kc * NBL);
        const float4* gm = (const float4*)(g_em + kc * NBL);
        #pragma unroll
        for (int it = 0; it < (KC * BM / 4) / NTHR; ++it) {    // 4 iters
            int idx = it * NTHR + tid;
            ((float4*)s_cp)[idx] = gc[idx];
            ((float4*)s_ep)[idx] = ge[idx];
            ((float4*)s_em)[idx] = gm[idx];
        }
        __syncthreads();

        #pragma unroll 1
        for (int kl = 0; kl < KC; ++kl) {
            const ulonglong2* vv = (const ulonglong2*)s_v + (kc + kl) * 32 + c;
            ulonglong2 q0 = vv[0];      // q.x=(em_v0,em_v1)  q.y=(ep_v0,ep_v1)
            ulonglong2 q1 = vv[8];
            ulonglong2 q2 = vv[16];
            ulonglong2 q3 = vv[24];

            const float* pc = s_cp + kl * BM + r0;
            const float* pe = s_ep + kl * BM + r0;
            const float* pm = s_em + kl * BM + r0;

            #pragma unroll
            for (int i = 0; i < 8; ++i) {
                float cs = pc[i], es = pe[i], ms = pm[i];
                u64 cpd = pk(cs, cs);
                u64 epd = pk(es, es);
                u64 emd = pk(ms, ms);

                {
                    u64 t1 = mul2(epd, q0.x), t2 = mul2(emd, q0.y);
                    float a0, a1, b0, b1; upk(t1, a0, a1); upk(t2, b0, b1);
                    acc[i][0] = fma2(cpd, pk(fminf(a0, b0), fminf(a1, b1)), acc[i][0]);
                }
                {
                    u64 t1 = mul2(epd, q1.x), t2 = mul2(emd, q1.y);
                    float a0, a1, b0, b1; upk(t1, a0, a1); upk(t2, b0, b1);
                    acc[i][1] = fma2(cpd, pk(fminf(a0, b0), fminf(a1, b1)), acc[i][1]);
                }
                {
                    u64 t1 = mul2(epd, q2.x), t2 = mul2(emd, q2.y);
                    float a0, a1, b0, b1; upk(t1, a0, a1); upk(t2, b0, b1);
                    acc[i][2] = fma2(cpd, pk(fminf(a0, b0), fminf(a1, b1)), acc[i][2]);
                }
                {
                    u64 t1 = mul2(epd, q3.x), t2 = mul2(emd, q3.y);
                    float a0, a1, b0, b1; upk(t1, a0, a1); upk(t2, b0, b1);
                    acc[i][3] = fma2(cpd, pk(fminf(a0, b0), fminf(a1, b1)), acc[i][3]);
                }
            }
        }
        __syncthreads();
    }

    // --- Epilogue: 8 rows x 8 contiguous cols, packed bias add, STG.128 ---
    const float bias = bptr[0];
    const u64 bias2 = pk(bias, bias);
    #pragma unroll
    for (int i = 0; i < 8; ++i) {
        long base = (long)(r0 + i) * VOCAB + vbase + c * 8;
        u64 a0 = add2(acc[i][0], bias2);
        u64 a1 = add2(acc[i][1], bias2);
        u64 a2 = add2(acc[i][2], bias2);
        u64 a3 = add2(acc[i][3], bias2);
        *(ulonglong2*)&out[base]     = make_ulonglong2(a0, a1);
        *(ulonglong2*)&out[base + 4] = make_ulonglong2(a2, a3);
    }
}

// ---------------------------------------------------------------------------
extern "C" void kernel_launch(void* const* d_in, const int* in_sizes, int n_in,
                              void* d_out, int out_size) {
    const float* freqs  = (const float*)d_in[0];
    const float* amps   = (const float*)d_in[1];
    const float* phases = (const float*)d_in[2];
    const float* vp     = (const float*)d_in[3];
    const float* iph    = (const float*)d_in[4];
    const float* W      = (const float*)d_in[5];
    const float* b      = (const float*)d_in[6];
    float* out = (float*)d_out;

    prep_bl<<<(NBL * NK) / 256, 256>>>(freqs, amps, phases, iph, W);

    const int smem_bytes = 32768 + 3 * KC * BM * (int)sizeof(float);   // 57344
    cudaFuncSetAttribute(main_kernel, cudaFuncAttributeMaxDynamicSharedMemorySize, smem_bytes);
    cudaFuncSetAttribute(main_kernel, cudaFuncAttributePreferredSharedMemoryCarveout, 100);

    main_kernel<<<VOCAB / BN, NTHR, smem_bytes>>>(out, vp, b);
    (void)in_sizes; (void)n_in; (void)out_size;
}